// round 16
// baseline (speedup 1.0000x reference)
#include <cuda_runtime.h>
#include <cuda_fp16.h>
#include <cstdint>
#include <math.h>

#define D_MODEL 1024
#define NH      16
#define DK      64
#define BB      2
#define SS      2048
#define MTOT    (BB * SS)
#define KLOG2   0.41524101186092155f   // log2(10000)/32
#define LOG2E   1.4426950408889634f

// ---------------------------------------------------------------------------
// Scratch (allocation-free rule: __device__ globals) — all single fp16
// ---------------------------------------------------------------------------
__device__ __half g_aq[MTOT * D_MODEL];
__device__ __half g_ak[MTOT * D_MODEL];
__device__ __half g_av[MTOT * D_MODEL];
__device__ __half g_wq[D_MODEL * D_MODEL];
__device__ __half g_wk[D_MODEL * D_MODEL];
__device__ __half g_wv[D_MODEL * D_MODEL];
__device__ __half g_wo[D_MODEL * D_MODEL];
__device__ __half g_qh[MTOT * D_MODEL];           // single fp16 Q (scaled 1/8)
__device__ __half g_kh[MTOT * D_MODEL];
__device__ __half g_v[MTOT * D_MODEL];
__device__ __half g_cx[MTOT * D_MODEL];

// ---------------------------------------------------------------------------
// Portable PTX helpers
// ---------------------------------------------------------------------------
__device__ __forceinline__ uint32_t smem_u32(const void* p) {
    uint32_t a;
    asm("{ .reg .u64 t; cvta.to.shared.u64 t, %1; cvt.u32.u64 %0, t; }" : "=r"(a) : "l"(p));
    return a;
}
#define CP_ASYNC16(dst, src) \
    asm volatile("cp.async.cg.shared.global [%0], [%1], 16;" :: "r"(dst), "l"(src))
#define CP_COMMIT() asm volatile("cp.async.commit_group;" ::: "memory")
#define CP_WAIT(n)  asm volatile("cp.async.wait_group %0;" :: "n"(n) : "memory")

__device__ __forceinline__ void ldm_x4(uint32_t* r, uint32_t addr) {
    asm volatile("ldmatrix.sync.aligned.m8n8.x4.shared.b16 {%0,%1,%2,%3}, [%4];"
                 : "=r"(r[0]), "=r"(r[1]), "=r"(r[2]), "=r"(r[3]) : "r"(addr));
}
__device__ __forceinline__ void ldm_x4t(uint32_t* r, uint32_t addr) {
    asm volatile("ldmatrix.sync.aligned.m8n8.x4.trans.shared.b16 {%0,%1,%2,%3}, [%4];"
                 : "=r"(r[0]), "=r"(r[1]), "=r"(r[2]), "=r"(r[3]) : "r"(addr));
}
__device__ __forceinline__ void mma16816h(float* d, const uint32_t* a, const uint32_t* b) {
    asm volatile(
        "mma.sync.aligned.m16n8k16.row.col.f32.f16.f16.f32 "
        "{%0,%1,%2,%3}, {%4,%5,%6,%7}, {%8,%9}, {%0,%1,%2,%3};"
        : "+f"(d[0]), "+f"(d[1]), "+f"(d[2]), "+f"(d[3])
        : "r"(a[0]), "r"(a[1]), "r"(a[2]), "r"(a[3]), "r"(b[0]), "r"(b[1]));
}
__device__ __forceinline__ uint32_t sw64(uint32_t off)  { return off ^ ((off >> 3) & 0x30); }
__device__ __forceinline__ uint32_t sw128(uint32_t off) { return off ^ ((off >> 3) & 0x70); }

__device__ __forceinline__ uint32_t pack_h2(float a, float b) {
    __half2 h = __floats2half2_rn(a, b);
    return *(uint32_t*)&h;
}
__device__ __forceinline__ float fex2(float x) {
    float r;
    asm("ex2.approx.f32 %0, %1;" : "=f"(r) : "f"(x));
    return r;
}

// ---------------------------------------------------------------------------
// Fused input conversions (single fp16)
// ---------------------------------------------------------------------------
__device__ __forceinline__ uint2 cvt4h(float4 v) {
    __half2 h0 = __floats2half2_rn(v.x, v.y);
    __half2 h1 = __floats2half2_rn(v.z, v.w);
    uint2 H;
    H.x = *(uint32_t*)&h0;
    H.y = *(uint32_t*)&h1;
    return H;
}

__global__ void split3_kernel(const float4* __restrict__ A, const float4* __restrict__ B,
                              const float4* __restrict__ C, int n4) {
    int i = blockIdx.x * blockDim.x + threadIdx.x;
    if (i >= n4) return;
    const float4* src = (blockIdx.y == 0) ? A : (blockIdx.y == 1) ? B : C;
    uint2* dh = (blockIdx.y == 0) ? (uint2*)g_aq : (blockIdx.y == 1) ? (uint2*)g_ak : (uint2*)g_av;
    dh[i] = cvt4h(src[i]);
}

__global__ void split4_kernel(const float4* __restrict__ A, const float4* __restrict__ B,
                              const float4* __restrict__ C, const float4* __restrict__ D, int n4) {
    int i = blockIdx.x * blockDim.x + threadIdx.x;
    if (i >= n4) return;
    int s = blockIdx.y;
    const float4* src = (s == 0) ? A : (s == 1) ? B : (s == 2) ? C : D;
    uint2* oh = (s == 0) ? (uint2*)g_wq : (s == 1) ? (uint2*)g_wk : (s == 2) ? (uint2*)g_wv : (uint2*)g_wo;
    oh[i] = cvt4h(src[i]);
}

// ---------------------------------------------------------------------------
// GEMM core — 1-term (A single x B single): 2 smem tiles per stage
// ---------------------------------------------------------------------------
#define GK        1024
#define BKC       32
#define NCH       (GK / BKC)
#define TILE8K    8192
#define NSTG      3
#define GEMM_SMEM (NSTG * 2 * TILE8K)    // 48KB

struct GemmCtx {
    uint32_t smb;
    uint32_t aoff[2][2], boff[4][2];
    const __half* gb[2];
    int lrow, lc;
};

__device__ __forceinline__ void gemm_mainloop(GemmCtx& cx, float acc[2][8][4]) {
    const int STAGE = 2 * TILE8K;
    auto load_stage = [&](int st, int ch) {
        const uint32_t sb = cx.smb + st * STAGE;
#pragma unroll
        for (int j = 0; j < 4; j++) {
            const int tile = j >> 1;
            const int rh = (j & 1) * 64 + cx.lrow;
            const __half* g = cx.gb[tile] + (size_t)rh * GK + ch * BKC + cx.lc * 8;
            const uint32_t dst = sb + tile * TILE8K + sw64(rh * 64 + cx.lc * 16);
            CP_ASYNC16(dst, g);
        }
        CP_COMMIT();
    };

    load_stage(0, 0);
    load_stage(1, 1);

    for (int ch = 0; ch < NCH; ch++) {
        if (ch < NCH - 2) { CP_WAIT(1); } else { CP_WAIT(0); }
        __syncthreads();
        if (ch + 2 < NCH) load_stage((ch + 2) % NSTG, ch + 2);

        const uint32_t sb = cx.smb + (ch % NSTG) * STAGE;
#pragma unroll
        for (int ks = 0; ks < 2; ks++) {
            uint32_t ah[2][4];
#pragma unroll
            for (int mf = 0; mf < 2; mf++)
                ldm_x4(ah[mf], sb + cx.aoff[mf][ks]);
#pragma unroll
            for (int nh = 0; nh < 2; nh++) {
                uint32_t bh[2][4];
#pragma unroll
                for (int p = 0; p < 2; p++)
                    ldm_x4(bh[p], sb + TILE8K + cx.boff[nh * 2 + p][ks]);
#pragma unroll
                for (int mf = 0; mf < 2; mf++)
#pragma unroll
                    for (int p = 0; p < 2; p++)
#pragma unroll
                        for (int q = 0; q < 2; q++)
                            mma16816h(acc[mf][nh * 4 + p * 2 + q], ah[mf], &bh[p][q * 2]);
            }
        }
    }
}

__device__ __forceinline__ void gemm_setup(GemmCtx& cx, const char* smc, int t,
                                           const __half* A, const __half* B,
                                           int m0, int n0) {
    cx.smb = smem_u32(smc);
    const int lane = t & 31, wid = t >> 5;
    const int warpM = wid >> 1, warpN = wid & 1;
    cx.lrow = t >> 2;
    cx.lc = t & 3;
    cx.gb[0] = A + (size_t)m0 * GK;
    cx.gb[1] = B + (size_t)n0 * GK;
#pragma unroll
    for (int mf = 0; mf < 2; mf++)
#pragma unroll
        for (int ks = 0; ks < 2; ks++)
            cx.aoff[mf][ks] = sw64((warpM * 32 + mf * 16 + (lane & 15)) * 64
                                   + ks * 32 + (lane >> 4) * 16);
#pragma unroll
    for (int p = 0; p < 4; p++)
#pragma unroll
        for (int ks = 0; ks < 2; ks++)
            cx.boff[p][ks] = sw64((warpN * 64 + p * 16 + ((lane >> 4) << 3) + (lane & 7)) * 64
                                  + ks * 32 + ((lane >> 3) & 1) * 16);
}

// ---------------------------------------------------------------------------
// Merged QKV projection GEMM (1-term). Epilogues: z=0 Q (RoPE/8), z=1 K (RoPE),
// z=2 V. All single-fp16 per-head outputs.
// ---------------------------------------------------------------------------
__global__ void __launch_bounds__(256, 2) gemm_qkv_kernel() {
    extern __shared__ char smc[];
    const int t = threadIdx.x;
    const int lane = t & 31, wid = t >> 5;
    const int warpM = wid >> 1, warpN = wid & 1;
    const int m0 = blockIdx.y * 128;
    const int n0 = blockIdx.x * 128;
    const int z = blockIdx.z;

    float acc[2][8][4];
#pragma unroll
    for (int mf = 0; mf < 2; mf++)
#pragma unroll
        for (int nf = 0; nf < 8; nf++)
#pragma unroll
            for (int r = 0; r < 4; r++) acc[mf][nf][r] = 0.0f;

    const __half* A = (z == 0) ? g_aq : (z == 1) ? g_ak : g_av;
    const __half* B = (z == 0) ? g_wq : (z == 1) ? g_wk : g_wv;

    GemmCtx cx;
    gemm_setup(cx, smc, t, A, B, m0, n0);
    gemm_mainloop(cx, acc);

    const int rbase = m0 + warpM * 32 + (lane >> 2);
    const int h = (n0 >> 6) + warpN;
    if (z < 2) {
        __half* O = (z == 0) ? g_qh : g_kh;
        const float scale = (z == 0) ? 0.125f : 1.0f;
#pragma unroll
        for (int mf = 0; mf < 2; mf++)
#pragma unroll
            for (int r2 = 0; r2 < 2; r2++) {
                const int gr = rbase + mf * 16 + r2 * 8;
                const int s = gr & (SS - 1), b = gr >> 11;
                const float fs = (float)s;
                __half* oh = O + ((size_t)(b * NH + h) * SS + s) * DK;
#pragma unroll
                for (int nf = 0; nf < 4; nf++) {
                    const int i0 = (lane & 3) * 2 + nf * 8;
                    float x1a = acc[mf][nf][2 * r2],     x1b = acc[mf][nf][2 * r2 + 1];
                    float x2a = acc[mf][nf + 4][2 * r2], x2b = acc[mf][nf + 4][2 * r2 + 1];
                    float sa, ca, sb2, cb;
                    sincosf(fs * exp2f(-(float)i0 * KLOG2), &sa, &ca);
                    sincosf(fs * exp2f(-(float)(i0 + 1) * KLOG2), &sb2, &cb);
                    float y1a = (x1a * ca - x2a * sa) * scale;
                    float y1b = (x1b * cb - x2b * sb2) * scale;
                    float y2a = (x2a * ca + x1a * sa) * scale;
                    float y2b = (x2b * cb + x1b * sb2) * scale;
                    *(uint32_t*)(oh + i0)      = pack_h2(y1a, y1b);
                    *(uint32_t*)(oh + i0 + 32) = pack_h2(y2a, y2b);
                }
            }
    } else {
#pragma unroll
        for (int mf = 0; mf < 2; mf++)
#pragma unroll
            for (int r2 = 0; r2 < 2; r2++) {
                const int gr = rbase + mf * 16 + r2 * 8;
                const int s = gr & (SS - 1), b = gr >> 11;
                __half* oh = g_v + ((size_t)(b * NH + h) * SS + s) * DK;
#pragma unroll
                for (int nf = 0; nf < 8; nf++) {
                    const int d = (lane & 3) * 2 + nf * 8;
                    *(uint32_t*)(oh + d) = pack_h2(acc[mf][nf][2 * r2], acc[mf][nf][2 * r2 + 1]);
                }
            }
    }
}

// ---------------------------------------------------------------------------
// Output GEMM: ctx (single fp16) x Wo (single fp16) -> fp32 out
// ---------------------------------------------------------------------------
__global__ void __launch_bounds__(256, 2) gemm_out_kernel(float* __restrict__ C) {
    extern __shared__ char smc[];
    const int t = threadIdx.x;
    const int lane = t & 31, wid = t >> 5;
    const int warpM = wid >> 1, warpN = wid & 1;
    const int m0 = blockIdx.y * 128;
    const int n0 = blockIdx.x * 128;

    GemmCtx cx;
    gemm_setup(cx, smc, t, g_cx, g_wo, m0, n0);

    float acc[2][8][4];
#pragma unroll
    for (int mf = 0; mf < 2; mf++)
#pragma unroll
        for (int nf = 0; nf < 8; nf++)
#pragma unroll
            for (int r = 0; r < 4; r++) acc[mf][nf][r] = 0.0f;

    gemm_mainloop(cx, acc);

    const int rbase = m0 + warpM * 32 + (lane >> 2);
    const int cbase = n0 + warpN * 64 + (lane & 3) * 2;
#pragma unroll
    for (int mf = 0; mf < 2; mf++)
#pragma unroll
        for (int nf = 0; nf < 8; nf++) {
            const int row = rbase + mf * 16;
            const int col = cbase + nf * 8;
            float2 v0 = {acc[mf][nf][0], acc[mf][nf][1]};
            float2 v1 = {acc[mf][nf][2], acc[mf][nf][3]};
            *(float2*)(C + (size_t)row * D_MODEL + col) = v0;
            *(float2*)(C + (size_t)(row + 8) * D_MODEL + col) = v1;
        }
}

// ---------------------------------------------------------------------------
// Tensor-core causal flash attention — 128 threads / 64 q-rows / 3 CTAs/SM
// (12 warps/SM). Per-warp instruction stream identical to R15.
// smem: Q 8KB + 2 stages x 16KB (K, V) = 40KB.
// ---------------------------------------------------------------------------
#define AT_STG   8192
#define AT_STGB  16384
#define AT_SMEM  (8192 + 2 * AT_STGB)   // 40KB

__global__ void __launch_bounds__(128, 3) attn_tc_kernel() {
    extern __shared__ char smc[];
    const uint32_t smb = smem_u32(smc);
    const int t = threadIdx.x, lane = t & 31, w = t >> 5;   // 4 warps
    const int bx = (int)gridDim.x - 1 - (int)blockIdx.x;    // heavy first
    const int bh = blockIdx.y;
    const int q0 = bx * 64;
    const int ntk = bx + 1;
    const size_t hoff = (size_t)bh * SS * DK;

    // ---- Q load: 64 rows x 128B = 8KB; 128 thr x 4 x 16B ----
    {
        int row = t >> 1;
        const __half* qsrc = g_qh + hoff + (size_t)(q0 + row) * DK;
#pragma unroll
        for (int j = 0; j < 4; j++) {
            int slot = (t & 1) * 4 + j;
            uint32_t sw = sw128(row * 128 + slot * 16);
            CP_ASYNC16(smb + sw, qsrc + slot * 8);
        }
    }
    // ---- KV stage: K 8KB + V 8KB; 128 thr x 8 x 16B ----
    const int kvrow = t >> 1;
    auto load_kv = [&](int st, int kt) {
        const uint32_t sb = smb + AT_STG + st * AT_STGB;
        const size_t g = hoff + (size_t)(kt * 64 + kvrow) * DK;
#pragma unroll
        for (int j = 0; j < 4; j++) {
            int slot = (t & 1) * 4 + j;
            uint32_t sw = sw128(kvrow * 128 + slot * 16);
            CP_ASYNC16(sb + 0 * 8192 + sw, g_kh + g + slot * 8);
            CP_ASYNC16(sb + 1 * 8192 + sw, g_v + g + slot * 8);
        }
        CP_COMMIT();
    };

    load_kv(0, 0);
    CP_WAIT(0);
    __syncthreads();

    uint32_t qh[4][4];
    {
        uint32_t base = (w * 16 + (lane & 15)) * 128 + (lane >> 4) * 16;
#pragma unroll
        for (int ks = 0; ks < 4; ks++)
            ldm_x4(qh[ks], smb + sw128(base + ks * 32));
    }

    float oacc[8][4];
#pragma unroll
    for (int nf = 0; nf < 8; nf++)
#pragma unroll
        for (int r = 0; r < 4; r++) oacc[nf][r] = 0.0f;
    float m0 = -1e30f, m1 = -1e30f, l0 = 0.0f, l1 = 0.0f;

    const int qw = q0 + w * 16;

    for (int ch = 0; ch < ntk; ch++) {
        __syncthreads();
        if (ch + 1 < ntk) load_kv((ch + 1) & 1, ch + 1);
        if (ch + 1 < ntk) { CP_WAIT(1); } else { CP_WAIT(0); }
        __syncthreads();

        const int k0g = ch * 64;
        const uint32_t stg = smb + AT_STG + (ch & 1) * AT_STGB;

        float sacc[8][4];
#pragma unroll
        for (int nf = 0; nf < 8; nf++)
#pragma unroll
            for (int r = 0; r < 4; r++) sacc[nf][r] = 0.0f;

        const uint32_t krow = ((lane >> 4) << 3) + (lane & 7);
        const uint32_t kcol = ((lane >> 3) & 1) * 16;
#pragma unroll
        for (int ks = 0; ks < 4; ks++) {
            uint32_t kh[4][4];
#pragma unroll
            for (int p = 0; p < 4; p++)
                ldm_x4(kh[p], stg + sw128((p * 16 + krow) * 128 + ks * 32 + kcol));
#pragma unroll
            for (int p = 0; p < 4; p++) {
                mma16816h(sacc[2 * p],     qh[ks], &kh[p][0]);
                mma16816h(sacc[2 * p + 1], qh[ks], &kh[p][2]);
            }
        }

        const int r0 = qw + (lane >> 2), r1 = r0 + 8;
        if (k0g + 63 > qw) {
#pragma unroll
            for (int nf = 0; nf < 8; nf++) {
                int key = k0g + nf * 8 + (lane & 3) * 2;
                if (key     > r0) sacc[nf][0] = -1e30f;
                if (key + 1 > r0) sacc[nf][1] = -1e30f;
                if (key     > r1) sacc[nf][2] = -1e30f;
                if (key + 1 > r1) sacc[nf][3] = -1e30f;
            }
        }

        float mx0 = -1e30f, mx1 = -1e30f;
#pragma unroll
        for (int nf = 0; nf < 8; nf++) {
            mx0 = fmaxf(mx0, fmaxf(sacc[nf][0], sacc[nf][1]));
            mx1 = fmaxf(mx1, fmaxf(sacc[nf][2], sacc[nf][3]));
        }
        mx0 = fmaxf(mx0, __shfl_xor_sync(0xffffffffu, mx0, 1));
        mx0 = fmaxf(mx0, __shfl_xor_sync(0xffffffffu, mx0, 2));
        mx1 = fmaxf(mx1, __shfl_xor_sync(0xffffffffu, mx1, 1));
        mx1 = fmaxf(mx1, __shfl_xor_sync(0xffffffffu, mx1, 2));
        float mn0 = fmaxf(m0, mx0), mn1 = fmaxf(m1, mx1);
        float mnc0 = mn0 * LOG2E, mnc1 = mn1 * LOG2E;
        float al0 = fex2(fmaf(m0, LOG2E, -mnc0));
        float al1 = fex2(fmaf(m1, LOG2E, -mnc1));
        m0 = mn0; m1 = mn1;

        float rs0 = 0.0f, rs1 = 0.0f;
#pragma unroll
        for (int nf = 0; nf < 8; nf++) {
            sacc[nf][0] = fex2(fmaf(sacc[nf][0], LOG2E, -mnc0));
            sacc[nf][1] = fex2(fmaf(sacc[nf][1], LOG2E, -mnc0));
            sacc[nf][2] = fex2(fmaf(sacc[nf][2], LOG2E, -mnc1));
            sacc[nf][3] = fex2(fmaf(sacc[nf][3], LOG2E, -mnc1));
            rs0 += sacc[nf][0] + sacc[nf][1];
            rs1 += sacc[nf][2] + sacc[nf][3];
        }
        rs0 += __shfl_xor_sync(0xffffffffu, rs0, 1);
        rs0 += __shfl_xor_sync(0xffffffffu, rs0, 2);
        rs1 += __shfl_xor_sync(0xffffffffu, rs1, 1);
        rs1 += __shfl_xor_sync(0xffffffffu, rs1, 2);
        l0 = l0 * al0 + rs0;
        l1 = l1 * al1 + rs1;

#pragma unroll
        for (int nf = 0; nf < 8; nf++) {
            oacc[nf][0] *= al0; oacc[nf][1] *= al0;
            oacc[nf][2] *= al1; oacc[nf][3] *= al1;
        }

        uint32_t ph[4][4];
#pragma unroll
        for (int kf = 0; kf < 4; kf++) {
#pragma unroll
            for (int half = 0; half < 2; half++) {
                const float* c = sacc[2 * kf + half];
                ph[kf][half * 2 + 0] = pack_h2(c[0], c[1]);
                ph[kf][half * 2 + 1] = pack_h2(c[2], c[3]);
            }
        }

        const uint32_t vrow = ((lane >> 3) & 1) * 8 + (lane & 7);
        const uint32_t vcol = (lane >> 4) * 16;
#pragma unroll
        for (int kf = 0; kf < 4; kf++) {
            uint32_t vh[4][4];
#pragma unroll
            for (int nb = 0; nb < 4; nb++)
                ldm_x4t(vh[nb], stg + 8192 + sw128((kf * 16 + vrow) * 128 + nb * 32 + vcol));
#pragma unroll
            for (int nb = 0; nb < 4; nb++) {
                mma16816h(oacc[2 * nb],     ph[kf], &vh[nb][0]);
                mma16816h(oacc[2 * nb + 1], ph[kf], &vh[nb][2]);
            }
        }
    }

    const int b = bh >> 4, h = bh & 15;
    const float inv0 = 1.0f / l0, inv1 = 1.0f / l1;
    const int row0 = q0 + w * 16 + (lane >> 2);
    const size_t off0 = ((size_t)(b * SS + row0)) * D_MODEL + h * DK + (lane & 3) * 2;
    const size_t off1 = off0 + 8 * D_MODEL;
#pragma unroll
    for (int nf = 0; nf < 8; nf++) {
        *(uint32_t*)(g_cx + off0 + nf * 8) = pack_h2(oacc[nf][0] * inv0, oacc[nf][1] * inv0);
        *(uint32_t*)(g_cx + off1 + nf * 8) = pack_h2(oacc[nf][2] * inv1, oacc[nf][3] * inv1);
    }
}

// ---------------------------------------------------------------------------
// Launch
// ---------------------------------------------------------------------------
extern "C" void kernel_launch(void* const* d_in, const int* in_sizes, int n_in,
                              void* d_out, int out_size) {
    const float* q  = (const float*)d_in[0];
    const float* k  = (const float*)d_in[1];
    const float* v  = (const float*)d_in[2];
    const float* Wq = (const float*)d_in[4];
    const float* Wk = (const float*)d_in[5];
    const float* Wv = (const float*)d_in[6];
    const float* Wo = (const float*)d_in[7];
    float* out = (float*)d_out;

    cudaFuncSetAttribute(gemm_qkv_kernel, cudaFuncAttributeMaxDynamicSharedMemorySize, GEMM_SMEM);
    cudaFuncSetAttribute(gemm_out_kernel, cudaFuncAttributeMaxDynamicSharedMemorySize, GEMM_SMEM);
    cudaFuncSetAttribute(attn_tc_kernel, cudaFuncAttributeMaxDynamicSharedMemorySize, AT_SMEM);

    const int nA4 = MTOT * D_MODEL / 4;
    const int nW4 = D_MODEL * D_MODEL / 4;

    split3_kernel<<<dim3((nA4 + 255) / 256, 3), 256>>>(
        (const float4*)q, (const float4*)k, (const float4*)v, nA4);
    split4_kernel<<<dim3((nW4 + 255) / 256, 4), 256>>>(
        (const float4*)Wq, (const float4*)Wk, (const float4*)Wv, (const float4*)Wo, nW4);

    gemm_qkv_kernel<<<dim3(D_MODEL / 128, MTOT / 128, 3), 256, GEMM_SMEM>>>();

    attn_tc_kernel<<<dim3(SS / 64, BB * NH), 128, AT_SMEM>>>();

    gemm_out_kernel<<<dim3(D_MODEL / 128, MTOT / 128), 256, GEMM_SMEM>>>(out);
}

// round 17
// speedup vs baseline: 1.0362x; 1.0362x over previous
#include <cuda_runtime.h>
#include <cuda_fp16.h>
#include <cstdint>
#include <math.h>

#define D_MODEL 1024
#define NH      16
#define DK      64
#define BB      2
#define SS      2048
#define MTOT    (BB * SS)
#define KLOG2   0.41524101186092155f   // log2(10000)/32
#define LOG2E   1.4426950408889634f

// ---------------------------------------------------------------------------
// Scratch (allocation-free rule: __device__ globals) — all single fp16
// ---------------------------------------------------------------------------
__device__ __half g_aq[MTOT * D_MODEL];
__device__ __half g_ak[MTOT * D_MODEL];
__device__ __half g_av[MTOT * D_MODEL];
__device__ __half g_wq[D_MODEL * D_MODEL];
__device__ __half g_wk[D_MODEL * D_MODEL];
__device__ __half g_wv[D_MODEL * D_MODEL];
__device__ __half g_wo[D_MODEL * D_MODEL];
__device__ __half g_qh[MTOT * D_MODEL];           // single fp16 Q (scaled 1/8)
__device__ __half g_kh[MTOT * D_MODEL];
__device__ __half g_v[MTOT * D_MODEL];
__device__ __half g_cx[MTOT * D_MODEL];

// ---------------------------------------------------------------------------
// Portable PTX helpers
// ---------------------------------------------------------------------------
__device__ __forceinline__ uint32_t smem_u32(const void* p) {
    uint32_t a;
    asm("{ .reg .u64 t; cvta.to.shared.u64 t, %1; cvt.u32.u64 %0, t; }" : "=r"(a) : "l"(p));
    return a;
}
#define CP_ASYNC16(dst, src) \
    asm volatile("cp.async.cg.shared.global [%0], [%1], 16;" :: "r"(dst), "l"(src))
#define CP_COMMIT() asm volatile("cp.async.commit_group;" ::: "memory")
#define CP_WAIT(n)  asm volatile("cp.async.wait_group %0;" :: "n"(n) : "memory")

__device__ __forceinline__ void ldm_x4(uint32_t* r, uint32_t addr) {
    asm volatile("ldmatrix.sync.aligned.m8n8.x4.shared.b16 {%0,%1,%2,%3}, [%4];"
                 : "=r"(r[0]), "=r"(r[1]), "=r"(r[2]), "=r"(r[3]) : "r"(addr));
}
__device__ __forceinline__ void ldm_x4t(uint32_t* r, uint32_t addr) {
    asm volatile("ldmatrix.sync.aligned.m8n8.x4.trans.shared.b16 {%0,%1,%2,%3}, [%4];"
                 : "=r"(r[0]), "=r"(r[1]), "=r"(r[2]), "=r"(r[3]) : "r"(addr));
}
__device__ __forceinline__ void mma16816h(float* d, const uint32_t* a, const uint32_t* b) {
    asm volatile(
        "mma.sync.aligned.m16n8k16.row.col.f32.f16.f16.f32 "
        "{%0,%1,%2,%3}, {%4,%5,%6,%7}, {%8,%9}, {%0,%1,%2,%3};"
        : "+f"(d[0]), "+f"(d[1]), "+f"(d[2]), "+f"(d[3])
        : "r"(a[0]), "r"(a[1]), "r"(a[2]), "r"(a[3]), "r"(b[0]), "r"(b[1]));
}
__device__ __forceinline__ uint32_t sw64(uint32_t off)  { return off ^ ((off >> 3) & 0x30); }
__device__ __forceinline__ uint32_t sw128(uint32_t off) { return off ^ ((off >> 3) & 0x70); }

__device__ __forceinline__ uint32_t pack_h2(float a, float b) {
    __half2 h = __floats2half2_rn(a, b);
    return *(uint32_t*)&h;
}
__device__ __forceinline__ float fex2(float x) {
    float r;
    asm("ex2.approx.f32 %0, %1;" : "=f"(r) : "f"(x));
    return r;
}
// packed fp16x2 ex2 (MUFU): two exps in one op, result pre-packed for MMA
__device__ __forceinline__ uint32_t fex2h2(uint32_t x) {
    uint32_t r;
    asm("ex2.approx.f16x2 %0, %1;" : "=r"(r) : "r"(x));
    return r;
}

// ---------------------------------------------------------------------------
// Fused input conversions (single fp16)
// ---------------------------------------------------------------------------
__device__ __forceinline__ uint2 cvt4h(float4 v) {
    __half2 h0 = __floats2half2_rn(v.x, v.y);
    __half2 h1 = __floats2half2_rn(v.z, v.w);
    uint2 H;
    H.x = *(uint32_t*)&h0;
    H.y = *(uint32_t*)&h1;
    return H;
}

__global__ void split3_kernel(const float4* __restrict__ A, const float4* __restrict__ B,
                              const float4* __restrict__ C, int n4) {
    int i = blockIdx.x * blockDim.x + threadIdx.x;
    if (i >= n4) return;
    const float4* src = (blockIdx.y == 0) ? A : (blockIdx.y == 1) ? B : C;
    uint2* dh = (blockIdx.y == 0) ? (uint2*)g_aq : (blockIdx.y == 1) ? (uint2*)g_ak : (uint2*)g_av;
    dh[i] = cvt4h(src[i]);
}

__global__ void split4_kernel(const float4* __restrict__ A, const float4* __restrict__ B,
                              const float4* __restrict__ C, const float4* __restrict__ D, int n4) {
    int i = blockIdx.x * blockDim.x + threadIdx.x;
    if (i >= n4) return;
    int s = blockIdx.y;
    const float4* src = (s == 0) ? A : (s == 1) ? B : (s == 2) ? C : D;
    uint2* oh = (s == 0) ? (uint2*)g_wq : (s == 1) ? (uint2*)g_wk : (s == 2) ? (uint2*)g_wv : (uint2*)g_wo;
    oh[i] = cvt4h(src[i]);
}

// ---------------------------------------------------------------------------
// GEMM core — 1-term (A single x B single): 2 smem tiles per stage
// ---------------------------------------------------------------------------
#define GK        1024
#define BKC       32
#define NCH       (GK / BKC)
#define TILE8K    8192
#define NSTG      3
#define GEMM_SMEM (NSTG * 2 * TILE8K)    // 48KB

struct GemmCtx {
    uint32_t smb;
    uint32_t aoff[2][2], boff[4][2];
    const __half* gb[2];
    int lrow, lc;
};

__device__ __forceinline__ void gemm_mainloop(GemmCtx& cx, float acc[2][8][4]) {
    const int STAGE = 2 * TILE8K;
    auto load_stage = [&](int st, int ch) {
        const uint32_t sb = cx.smb + st * STAGE;
#pragma unroll
        for (int j = 0; j < 4; j++) {
            const int tile = j >> 1;
            const int rh = (j & 1) * 64 + cx.lrow;
            const __half* g = cx.gb[tile] + (size_t)rh * GK + ch * BKC + cx.lc * 8;
            const uint32_t dst = sb + tile * TILE8K + sw64(rh * 64 + cx.lc * 16);
            CP_ASYNC16(dst, g);
        }
        CP_COMMIT();
    };

    load_stage(0, 0);
    load_stage(1, 1);

    for (int ch = 0; ch < NCH; ch++) {
        if (ch < NCH - 2) { CP_WAIT(1); } else { CP_WAIT(0); }
        __syncthreads();
        if (ch + 2 < NCH) load_stage((ch + 2) % NSTG, ch + 2);

        const uint32_t sb = cx.smb + (ch % NSTG) * STAGE;
#pragma unroll
        for (int ks = 0; ks < 2; ks++) {
            uint32_t ah[2][4];
#pragma unroll
            for (int mf = 0; mf < 2; mf++)
                ldm_x4(ah[mf], sb + cx.aoff[mf][ks]);
#pragma unroll
            for (int nh = 0; nh < 2; nh++) {
                uint32_t bh[2][4];
#pragma unroll
                for (int p = 0; p < 2; p++)
                    ldm_x4(bh[p], sb + TILE8K + cx.boff[nh * 2 + p][ks]);
#pragma unroll
                for (int mf = 0; mf < 2; mf++)
#pragma unroll
                    for (int p = 0; p < 2; p++)
#pragma unroll
                        for (int q = 0; q < 2; q++)
                            mma16816h(acc[mf][nh * 4 + p * 2 + q], ah[mf], &bh[p][q * 2]);
            }
        }
    }
}

__device__ __forceinline__ void gemm_setup(GemmCtx& cx, const char* smc, int t,
                                           const __half* A, const __half* B,
                                           int m0, int n0) {
    cx.smb = smem_u32(smc);
    const int lane = t & 31, wid = t >> 5;
    const int warpM = wid >> 1, warpN = wid & 1;
    cx.lrow = t >> 2;
    cx.lc = t & 3;
    cx.gb[0] = A + (size_t)m0 * GK;
    cx.gb[1] = B + (size_t)n0 * GK;
#pragma unroll
    for (int mf = 0; mf < 2; mf++)
#pragma unroll
        for (int ks = 0; ks < 2; ks++)
            cx.aoff[mf][ks] = sw64((warpM * 32 + mf * 16 + (lane & 15)) * 64
                                   + ks * 32 + (lane >> 4) * 16);
#pragma unroll
    for (int p = 0; p < 4; p++)
#pragma unroll
        for (int ks = 0; ks < 2; ks++)
            cx.boff[p][ks] = sw64((warpN * 64 + p * 16 + ((lane >> 4) << 3) + (lane & 7)) * 64
                                  + ks * 32 + ((lane >> 3) & 1) * 16);
}

// ---------------------------------------------------------------------------
// Merged QKV projection GEMM (1-term). Epilogues: z=0 Q (RoPE/8), z=1 K (RoPE),
// z=2 V. All single-fp16 per-head outputs.
// ---------------------------------------------------------------------------
__global__ void __launch_bounds__(256, 2) gemm_qkv_kernel() {
    extern __shared__ char smc[];
    const int t = threadIdx.x;
    const int lane = t & 31, wid = t >> 5;
    const int warpM = wid >> 1, warpN = wid & 1;
    const int m0 = blockIdx.y * 128;
    const int n0 = blockIdx.x * 128;
    const int z = blockIdx.z;

    float acc[2][8][4];
#pragma unroll
    for (int mf = 0; mf < 2; mf++)
#pragma unroll
        for (int nf = 0; nf < 8; nf++)
#pragma unroll
            for (int r = 0; r < 4; r++) acc[mf][nf][r] = 0.0f;

    const __half* A = (z == 0) ? g_aq : (z == 1) ? g_ak : g_av;
    const __half* B = (z == 0) ? g_wq : (z == 1) ? g_wk : g_wv;

    GemmCtx cx;
    gemm_setup(cx, smc, t, A, B, m0, n0);
    gemm_mainloop(cx, acc);

    const int rbase = m0 + warpM * 32 + (lane >> 2);
    const int h = (n0 >> 6) + warpN;
    if (z < 2) {
        __half* O = (z == 0) ? g_qh : g_kh;
        const float scale = (z == 0) ? 0.125f : 1.0f;
#pragma unroll
        for (int mf = 0; mf < 2; mf++)
#pragma unroll
            for (int r2 = 0; r2 < 2; r2++) {
                const int gr = rbase + mf * 16 + r2 * 8;
                const int s = gr & (SS - 1), b = gr >> 11;
                const float fs = (float)s;
                __half* oh = O + ((size_t)(b * NH + h) * SS + s) * DK;
#pragma unroll
                for (int nf = 0; nf < 4; nf++) {
                    const int i0 = (lane & 3) * 2 + nf * 8;
                    float x1a = acc[mf][nf][2 * r2],     x1b = acc[mf][nf][2 * r2 + 1];
                    float x2a = acc[mf][nf + 4][2 * r2], x2b = acc[mf][nf + 4][2 * r2 + 1];
                    float sa, ca, sb2, cb;
                    sincosf(fs * exp2f(-(float)i0 * KLOG2), &sa, &ca);
                    sincosf(fs * exp2f(-(float)(i0 + 1) * KLOG2), &sb2, &cb);
                    float y1a = (x1a * ca - x2a * sa) * scale;
                    float y1b = (x1b * cb - x2b * sb2) * scale;
                    float y2a = (x2a * ca + x1a * sa) * scale;
                    float y2b = (x2b * cb + x1b * sb2) * scale;
                    *(uint32_t*)(oh + i0)      = pack_h2(y1a, y1b);
                    *(uint32_t*)(oh + i0 + 32) = pack_h2(y2a, y2b);
                }
            }
    } else {
#pragma unroll
        for (int mf = 0; mf < 2; mf++)
#pragma unroll
            for (int r2 = 0; r2 < 2; r2++) {
                const int gr = rbase + mf * 16 + r2 * 8;
                const int s = gr & (SS - 1), b = gr >> 11;
                __half* oh = g_v + ((size_t)(b * NH + h) * SS + s) * DK;
#pragma unroll
                for (int nf = 0; nf < 8; nf++) {
                    const int d = (lane & 3) * 2 + nf * 8;
                    *(uint32_t*)(oh + d) = pack_h2(acc[mf][nf][2 * r2], acc[mf][nf][2 * r2 + 1]);
                }
            }
    }
}

// ---------------------------------------------------------------------------
// Output GEMM: ctx (single fp16) x Wo (single fp16) -> fp32 out
// ---------------------------------------------------------------------------
__global__ void __launch_bounds__(256, 2) gemm_out_kernel(float* __restrict__ C) {
    extern __shared__ char smc[];
    const int t = threadIdx.x;
    const int lane = t & 31, wid = t >> 5;
    const int warpM = wid >> 1, warpN = wid & 1;
    const int m0 = blockIdx.y * 128;
    const int n0 = blockIdx.x * 128;

    GemmCtx cx;
    gemm_setup(cx, smc, t, g_cx, g_wo, m0, n0);

    float acc[2][8][4];
#pragma unroll
    for (int mf = 0; mf < 2; mf++)
#pragma unroll
        for (int nf = 0; nf < 8; nf++)
#pragma unroll
            for (int r = 0; r < 4; r++) acc[mf][nf][r] = 0.0f;

    gemm_mainloop(cx, acc);

    const int rbase = m0 + warpM * 32 + (lane >> 2);
    const int cbase = n0 + warpN * 64 + (lane & 3) * 2;
#pragma unroll
    for (int mf = 0; mf < 2; mf++)
#pragma unroll
        for (int nf = 0; nf < 8; nf++) {
            const int row = rbase + mf * 16;
            const int col = cbase + nf * 8;
            float2 v0 = {acc[mf][nf][0], acc[mf][nf][1]};
            float2 v1 = {acc[mf][nf][2], acc[mf][nf][3]};
            *(float2*)(C + (size_t)row * D_MODEL + col) = v0;
            *(float2*)(C + (size_t)(row + 8) * D_MODEL + col) = v1;
        }
}

// ---------------------------------------------------------------------------
// Tensor-core causal flash attention — R15 shape (256 thr / 128 q-rows).
// Softmax: exp via ex2.approx.f16x2 (pre-packed P); row sums via MMA B=ones.
// smem: Q 16KB + 2 stages x 16KB (K, V) = 48KB.
// ---------------------------------------------------------------------------
#define AT_STG   16384
#define AT_STGB  16384
#define AT_SMEM  (16384 + 2 * AT_STGB)   // 48KB

__global__ void __launch_bounds__(256, 1) attn_tc_kernel() {
    extern __shared__ char smc[];
    const uint32_t smb = smem_u32(smc);
    const int t = threadIdx.x, lane = t & 31, w = t >> 5;
    const int bx = (int)gridDim.x - 1 - (int)blockIdx.x;
    const int bh = blockIdx.y;
    const int q0 = bx * 128;
    const int ntk = 2 * bx + 2;
    const size_t hoff = (size_t)bh * SS * DK;

    {
        int row = t >> 1;
        const __half* qsrc = g_qh + hoff + (size_t)(q0 + row) * DK;
#pragma unroll
        for (int j = 0; j < 4; j++) {
            int slot = (t & 1) * 4 + j;
            uint32_t sw = sw128(row * 128 + slot * 16);
            CP_ASYNC16(smb + sw, qsrc + slot * 8);
        }
    }
    const int kvrow = t >> 2;
    const int kvs0 = t & 3;
    auto load_kv = [&](int st, int kt) {
        const uint32_t sb = smb + AT_STG + st * AT_STGB;
        const size_t g = hoff + (size_t)(kt * 64 + kvrow) * DK;
#pragma unroll
        for (int j = 0; j < 2; j++) {
            int slot = kvs0 + j * 4;
            uint32_t sw = sw128(kvrow * 128 + slot * 16);
            CP_ASYNC16(sb + 0 * 8192 + sw, g_kh + g + slot * 8);
            CP_ASYNC16(sb + 1 * 8192 + sw, g_v + g + slot * 8);
        }
        CP_COMMIT();
    };

    load_kv(0, 0);
    CP_WAIT(0);
    __syncthreads();

    uint32_t qh[4][4];
    {
        uint32_t base = (w * 16 + (lane & 15)) * 128 + (lane >> 4) * 16;
#pragma unroll
        for (int ks = 0; ks < 4; ks++)
            ldm_x4(qh[ks], smb + sw128(base + ks * 32));
    }

    float oacc[8][4];
#pragma unroll
    for (int nf = 0; nf < 8; nf++)
#pragma unroll
        for (int r = 0; r < 4; r++) oacc[nf][r] = 0.0f;
    float m0 = -1e30f, m1 = -1e30f, l0 = 0.0f, l1 = 0.0f;

    const uint32_t ones2 = 0x3C003C00u;            // half2(1, 1)
    const uint32_t bones[2] = {ones2, ones2};      // B-fragment of all-ones

    const int qw = q0 + w * 16;

    for (int ch = 0; ch < ntk; ch++) {
        __syncthreads();
        if (ch + 1 < ntk) load_kv((ch + 1) & 1, ch + 1);
        if (ch + 1 < ntk) { CP_WAIT(1); } else { CP_WAIT(0); }
        __syncthreads();

        const int k0g = ch * 64;
        if (k0g > qw + 15) continue;

        const uint32_t stg = smb + AT_STG + (ch & 1) * AT_STGB;

        float sacc[8][4];
#pragma unroll
        for (int nf = 0; nf < 8; nf++)
#pragma unroll
            for (int r = 0; r < 4; r++) sacc[nf][r] = 0.0f;

        const uint32_t krow = ((lane >> 4) << 3) + (lane & 7);
        const uint32_t kcol = ((lane >> 3) & 1) * 16;
#pragma unroll
        for (int ks = 0; ks < 4; ks++) {
            uint32_t kh[4][4];
#pragma unroll
            for (int p = 0; p < 4; p++)
                ldm_x4(kh[p], stg + sw128((p * 16 + krow) * 128 + ks * 32 + kcol));
#pragma unroll
            for (int p = 0; p < 4; p++) {
                mma16816h(sacc[2 * p],     qh[ks], &kh[p][0]);
                mma16816h(sacc[2 * p + 1], qh[ks], &kh[p][2]);
            }
        }

        const int r0 = qw + (lane >> 2), r1 = r0 + 8;
        if (k0g + 63 > qw) {
#pragma unroll
            for (int nf = 0; nf < 8; nf++) {
                int key = k0g + nf * 8 + (lane & 3) * 2;
                if (key     > r0) sacc[nf][0] = -1e30f;
                if (key + 1 > r0) sacc[nf][1] = -1e30f;
                if (key     > r1) sacc[nf][2] = -1e30f;
                if (key + 1 > r1) sacc[nf][3] = -1e30f;
            }
        }

        // ---- online max (fp32) ----
        float mx0 = -1e30f, mx1 = -1e30f;
#pragma unroll
        for (int nf = 0; nf < 8; nf++) {
            mx0 = fmaxf(mx0, fmaxf(sacc[nf][0], sacc[nf][1]));
            mx1 = fmaxf(mx1, fmaxf(sacc[nf][2], sacc[nf][3]));
        }
        mx0 = fmaxf(mx0, __shfl_xor_sync(0xffffffffu, mx0, 1));
        mx0 = fmaxf(mx0, __shfl_xor_sync(0xffffffffu, mx0, 2));
        mx1 = fmaxf(mx1, __shfl_xor_sync(0xffffffffu, mx1, 1));
        mx1 = fmaxf(mx1, __shfl_xor_sync(0xffffffffu, mx1, 2));
        float mn0 = fmaxf(m0, mx0), mn1 = fmaxf(m1, mx1);
        float mnc0 = mn0 * LOG2E, mnc1 = mn1 * LOG2E;
        float al0 = fex2(fmaf(m0, LOG2E, -mnc0));
        float al1 = fex2(fmaf(m1, LOG2E, -mnc1));
        m0 = mn0; m1 = mn1;

        // ---- exp via fp16x2 MUFU: P emerges pre-packed ----
        // frag order: [half*2+0] = rows r0 (c0, c1); [half*2+1] = rows r1 (c2, c3)
        uint32_t ph[4][4];
#pragma unroll
        for (int nf = 0; nf < 8; nf++) {
            const int kf = nf >> 1, half = nf & 1;
            float t0 = fmaf(sacc[nf][0], LOG2E, -mnc0);
            float t1 = fmaf(sacc[nf][1], LOG2E, -mnc0);
            float t2 = fmaf(sacc[nf][2], LOG2E, -mnc1);
            float t3 = fmaf(sacc[nf][3], LOG2E, -mnc1);
            ph[kf][half * 2 + 0] = fex2h2(pack_h2(t0, t1));
            ph[kf][half * 2 + 1] = fex2h2(pack_h2(t2, t3));
        }

        // ---- rescale O ----
#pragma unroll
        for (int nf = 0; nf < 8; nf++) {
            oacc[nf][0] *= al0; oacc[nf][1] *= al0;
            oacc[nf][2] *= al1; oacc[nf][3] *= al1;
        }

        // ---- O += P V (1-term) + row sums via B = ones ----
        float rsacc[4] = {0.0f, 0.0f, 0.0f, 0.0f};
        const uint32_t vrow = ((lane >> 3) & 1) * 8 + (lane & 7);
        const uint32_t vcol = (lane >> 4) * 16;
#pragma unroll
        for (int kf = 0; kf < 4; kf++) {
            uint32_t vh[4][4];
#pragma unroll
            for (int nb = 0; nb < 4; nb++)
                ldm_x4t(vh[nb], stg + 8192 + sw128((kf * 16 + vrow) * 128 + nb * 32 + vcol));
            mma16816h(rsacc, ph[kf], bones);       // row sums of P chunk
#pragma unroll
            for (int nb = 0; nb < 4; nb++) {
                mma16816h(oacc[2 * nb],     ph[kf], &vh[nb][0]);
                mma16816h(oacc[2 * nb + 1], ph[kf], &vh[nb][2]);
            }
        }
        l0 = l0 * al0 + rsacc[0];                  // all cols equal; [0] = rows r0
        l1 = l1 * al1 + rsacc[2];                  // [2] = rows r1
    }

    const int b = bh >> 4, h = bh & 15;
    const float inv0 = 1.0f / l0, inv1 = 1.0f / l1;
    const int row0 = q0 + w * 16 + (lane >> 2);
    const size_t off0 = ((size_t)(b * SS + row0)) * D_MODEL + h * DK + (lane & 3) * 2;
    const size_t off1 = off0 + 8 * D_MODEL;
#pragma unroll
    for (int nf = 0; nf < 8; nf++) {
        *(uint32_t*)(g_cx + off0 + nf * 8) = pack_h2(oacc[nf][0] * inv0, oacc[nf][1] * inv0);
        *(uint32_t*)(g_cx + off1 + nf * 8) = pack_h2(oacc[nf][2] * inv1, oacc[nf][3] * inv1);
    }
}

// ---------------------------------------------------------------------------
// Launch
// ---------------------------------------------------------------------------
extern "C" void kernel_launch(void* const* d_in, const int* in_sizes, int n_in,
                              void* d_out, int out_size) {
    const float* q  = (const float*)d_in[0];
    const float* k  = (const float*)d_in[1];
    const float* v  = (const float*)d_in[2];
    const float* Wq = (const float*)d_in[4];
    const float* Wk = (const float*)d_in[5];
    const float* Wv = (const float*)d_in[6];
    const float* Wo = (const float*)d_in[7];
    float* out = (float*)d_out;

    cudaFuncSetAttribute(gemm_qkv_kernel, cudaFuncAttributeMaxDynamicSharedMemorySize, GEMM_SMEM);
    cudaFuncSetAttribute(gemm_out_kernel, cudaFuncAttributeMaxDynamicSharedMemorySize, GEMM_SMEM);
    cudaFuncSetAttribute(attn_tc_kernel, cudaFuncAttributeMaxDynamicSharedMemorySize, AT_SMEM);

    const int nA4 = MTOT * D_MODEL / 4;
    const int nW4 = D_MODEL * D_MODEL / 4;

    split3_kernel<<<dim3((nA4 + 255) / 256, 3), 256>>>(
        (const float4*)q, (const float4*)k, (const float4*)v, nA4);
    split4_kernel<<<dim3((nW4 + 255) / 256, 4), 256>>>(
        (const float4*)Wq, (const float4*)Wk, (const float4*)Wv, (const float4*)Wo, nW4);

    gemm_qkv_kernel<<<dim3(D_MODEL / 128, MTOT / 128, 3), 256, GEMM_SMEM>>>();

    attn_tc_kernel<<<dim3(SS / 128, BB * NH), 256, AT_SMEM>>>();

    gemm_out_kernel<<<dim3(D_MODEL / 128, MTOT / 128), 256, GEMM_SMEM>>>(out);
}